// round 3
// baseline (speedup 1.0000x reference)
#include <cuda_runtime.h>
#include <cuda_bf16.h>
#include <math.h>

// ---------------- model constants ----------------
#define NL 2
#define DM 2560
#define DI 5120
#define DS 16
#define DC 4
#define DR 160
#define XP 192          // DR + 2*DS
#define BB 2
#define LL 512
#define BL 1024         // BB*LL
#define KS 8            // split-K factor for x_proj

// ---------------- scratch (device globals; no allocation) ----------------
__device__ float g_x[BL * DM];            // residual stream
__device__ float g_h[BL * DM];            // normed activations
__device__ float g_xz[(size_t)BL * 2 * DI];
__device__ float g_xc[BL * DI];           // conv+silu output (= u)
__device__ float g_delta[BL * DI];
__device__ float g_y[BL * DI];            // gated scan output
__device__ float g_xdbl[BL * XP];
__device__ float g_part[(size_t)KS * BL * XP];
__device__ float g_pool[BB * DM];

__device__ __forceinline__ float ex2f(float x) {
    float r; asm("ex2.approx.f32 %0, %1;" : "=f"(r) : "f"(x)); return r;
}
__device__ __forceinline__ float sigmoidf_(float x) {
    return 1.f / (1.f + __expf(-x));
}

__device__ __forceinline__ float block_sum256(float v) {
    __shared__ float sh[8];
    #pragma unroll
    for (int o = 16; o > 0; o >>= 1) v += __shfl_xor_sync(0xffffffffu, v, o);
    __syncthreads();                 // protect sh reuse across calls
    if ((threadIdx.x & 31) == 0) sh[threadIdx.x >> 5] = v;
    __syncthreads();
    v = sh[threadIdx.x & 7];
    #pragma unroll
    for (int o = 4; o > 0; o >>= 1) v += __shfl_xor_sync(0xffffffffu, v, o);
    return v;
}

// ---------------- embedding gather ----------------
__global__ void __launch_bounds__(256) embed_kernel(const float* __restrict__ emb,
                                                    const int* __restrict__ ids) {
    int idx = blockIdx.x * 256 + threadIdx.x;     // float4 units, total BL*DM/4
    int row = idx / (DM / 4);
    int c   = idx % (DM / 4);
    int id  = ids[row];
    ((float4*)g_x)[idx] = ((const float4*)(emb + (size_t)id * DM))[c];
}

// ---------------- rmsnorm: g_x -> g_h ----------------
__global__ void __launch_bounds__(256) rmsnorm_kernel(const float* __restrict__ w) {
    int row = blockIdx.x;
    const float* xr = g_x + (size_t)row * DM;
    float s = 0.f;
    #pragma unroll
    for (int q = 0; q < DM / 256; q++) {
        float v = xr[threadIdx.x + q * 256];
        s += v * v;
    }
    float tot = block_sum256(s);
    float inv = rsqrtf(tot * (1.f / DM) + 1e-5f);
    float* o = g_h + (size_t)row * DM;
    #pragma unroll
    for (int q = 0; q < DM / 256; q++) {
        int k = threadIdx.x + q * 256;
        o[k] = xr[k] * inv * w[k];
    }
}

// ---------------- 128x128x16 SGEMM (NT), 8x8 microtile ----------------
// MODE 0: g_h  @ in_proj^T  -> g_xz     (K=DM,  lda=DM,  ldc=2*DI, plain store)
// MODE 1: g_xdbl[:, :160] @ dt_proj^T -> g_delta (K=DR, lda=XP, ldc=DI, softplus(.+bias))
// MODE 2: g_y  @ out_proj^T -> g_x     (K=DI,  lda=DI,  ldc=DM,  residual +=)
template <int MODE>
__global__ void __launch_bounds__(256) gemm_tile(const float* __restrict__ W,
                                                 const float* __restrict__ bias) {
    constexpr int K   = (MODE == 0) ? DM : (MODE == 1) ? DR : DI;
    constexpr int LDA = (MODE == 0) ? DM : (MODE == 1) ? XP : DI;
    constexpr int LDC = (MODE == 0) ? 2 * DI : (MODE == 1) ? DI : DM;
    const float* __restrict__ A = (MODE == 0) ? g_h : (MODE == 1) ? g_xdbl : g_y;
    float* __restrict__ C       = (MODE == 0) ? g_xz : (MODE == 1) ? g_delta : g_x;

    __shared__ float As[16][132];
    __shared__ float Bs[16][132];
    const int bm  = blockIdx.y * 128;
    const int bn  = blockIdx.x * 128;
    const int tid = threadIdx.x;
    const int tx  = tid & 15;
    const int ty  = tid >> 4;
    const int lr  = tid >> 2;
    const int lc  = (tid & 3) * 4;

    float acc[8][8];
    #pragma unroll
    for (int i = 0; i < 8; i++)
        #pragma unroll
        for (int j = 0; j < 8; j++) acc[i][j] = 0.f;

    for (int k0 = 0; k0 < K; k0 += 16) {
        #pragma unroll
        for (int rr = 0; rr < 2; rr++) {
            float4 va = *(const float4*)&A[(size_t)(bm + lr + rr * 64) * LDA + k0 + lc];
            As[lc + 0][lr + rr * 64] = va.x; As[lc + 1][lr + rr * 64] = va.y;
            As[lc + 2][lr + rr * 64] = va.z; As[lc + 3][lr + rr * 64] = va.w;
            float4 vb = *(const float4*)&W[(size_t)(bn + lr + rr * 64) * K + k0 + lc];
            Bs[lc + 0][lr + rr * 64] = vb.x; Bs[lc + 1][lr + rr * 64] = vb.y;
            Bs[lc + 2][lr + rr * 64] = vb.z; Bs[lc + 3][lr + rr * 64] = vb.w;
        }
        __syncthreads();
        #pragma unroll
        for (int k = 0; k < 16; k++) {
            float4 a0 = *(const float4*)&As[k][ty * 8];
            float4 a1 = *(const float4*)&As[k][ty * 8 + 4];
            float4 b0 = *(const float4*)&Bs[k][tx * 8];
            float4 b1 = *(const float4*)&Bs[k][tx * 8 + 4];
            float ar[8] = {a0.x, a0.y, a0.z, a0.w, a1.x, a1.y, a1.z, a1.w};
            float br[8] = {b0.x, b0.y, b0.z, b0.w, b1.x, b1.y, b1.z, b1.w};
            #pragma unroll
            for (int i = 0; i < 8; i++)
                #pragma unroll
                for (int j = 0; j < 8; j++) acc[i][j] += ar[i] * br[j];
        }
        __syncthreads();
    }

    #pragma unroll
    for (int i = 0; i < 8; i++) {
        size_t row = bm + ty * 8 + i;
        #pragma unroll
        for (int jj = 0; jj < 2; jj++) {
            int col = bn + tx * 8 + jj * 4;
            float v0 = acc[i][jj * 4 + 0], v1 = acc[i][jj * 4 + 1];
            float v2 = acc[i][jj * 4 + 2], v3 = acc[i][jj * 4 + 3];
            float* cp = &C[row * LDC + col];
            if (MODE == 1) {
                v0 += bias[col + 0]; v1 += bias[col + 1];
                v2 += bias[col + 2]; v3 += bias[col + 3];
                v0 = (v0 > 20.f) ? v0 : log1pf(__expf(v0));
                v1 = (v1 > 20.f) ? v1 : log1pf(__expf(v1));
                v2 = (v2 > 20.f) ? v2 : log1pf(__expf(v2));
                v3 = (v3 > 20.f) ? v3 : log1pf(__expf(v3));
            }
            if (MODE == 2) {
                float4 o = *(const float4*)cp;
                v0 += o.x; v1 += o.y; v2 += o.z; v3 += o.w;
            }
            *(float4*)cp = make_float4(v0, v1, v2, v3);
        }
    }
}

// ---------------- depthwise causal conv1d + SiLU : g_xz[:, :DI] -> g_xc ----------------
__global__ void __launch_bounds__(256) conv_silu_kernel(const float* __restrict__ cw,
                                                        const float* __restrict__ cb) {
    int idx = blockIdx.x * 256 + threadIdx.x;   // over BL*DI
    int d = idx % DI;
    int r = idx / DI;                            // b*L + t
    int t = r & (LL - 1);
    float4 wv4 = ((const float4*)cw)[d];
    float wv[4] = {wv4.x, wv4.y, wv4.z, wv4.w};
    float acc = cb[d];
    if (t >= 3) {
        acc += wv[0] * g_xz[(size_t)(r - 3) * 2 * DI + d]
             + wv[1] * g_xz[(size_t)(r - 2) * 2 * DI + d]
             + wv[2] * g_xz[(size_t)(r - 1) * 2 * DI + d]
             + wv[3] * g_xz[(size_t)(r    ) * 2 * DI + d];
    } else {
        #pragma unroll
        for (int k = 0; k < 4; k++) {
            int tt = t - 3 + k;
            if (tt >= 0) acc += wv[k] * g_xz[(size_t)(r - 3 + k) * 2 * DI + d];
        }
    }
    g_xc[idx] = acc * sigmoidf_(acc);
}

// ---------------- x_proj split-K: g_xc @ x_proj^T -> g_part ----------------
__global__ void __launch_bounds__(256) gemm_xproj(const float* __restrict__ W) {
    __shared__ float As[16][132];
    __shared__ float Bs[16][68];
    const int bn  = blockIdx.x * 64;   // 0..2
    const int bm  = blockIdx.y * 128;  // 0..7
    const int ks  = blockIdx.z;        // 0..7
    const int tid = threadIdx.x;
    const int tx  = tid & 15;
    const int ty  = tid >> 4;
    const int lr  = tid >> 2;
    const int lc  = (tid & 3) * 4;

    float acc[8][4];
    #pragma unroll
    for (int i = 0; i < 8; i++)
        #pragma unroll
        for (int j = 0; j < 4; j++) acc[i][j] = 0.f;

    const int kb = ks * (DI / KS);
    for (int k0 = kb; k0 < kb + DI / KS; k0 += 16) {
        #pragma unroll
        for (int rr = 0; rr < 2; rr++) {
            float4 va = *(const float4*)&g_xc[(size_t)(bm + lr + rr * 64) * DI + k0 + lc];
            As[lc + 0][lr + rr * 64] = va.x; As[lc + 1][lr + rr * 64] = va.y;
            As[lc + 2][lr + rr * 64] = va.z; As[lc + 3][lr + rr * 64] = va.w;
        }
        {
            float4 vb = *(const float4*)&W[(size_t)(bn + lr) * DI + k0 + lc];
            Bs[lc + 0][lr] = vb.x; Bs[lc + 1][lr] = vb.y;
            Bs[lc + 2][lr] = vb.z; Bs[lc + 3][lr] = vb.w;
        }
        __syncthreads();
        #pragma unroll
        for (int k = 0; k < 16; k++) {
            float4 a0 = *(const float4*)&As[k][ty * 8];
            float4 a1 = *(const float4*)&As[k][ty * 8 + 4];
            float4 b0 = *(const float4*)&Bs[k][tx * 4];
            float ar[8] = {a0.x, a0.y, a0.z, a0.w, a1.x, a1.y, a1.z, a1.w};
            float br[4] = {b0.x, b0.y, b0.z, b0.w};
            #pragma unroll
            for (int i = 0; i < 8; i++)
                #pragma unroll
                for (int j = 0; j < 4; j++) acc[i][j] += ar[i] * br[j];
        }
        __syncthreads();
    }
    #pragma unroll
    for (int i = 0; i < 8; i++) {
        *(float4*)&g_part[((size_t)ks * BL + bm + ty * 8 + i) * XP + bn + tx * 4] =
            make_float4(acc[i][0], acc[i][1], acc[i][2], acc[i][3]);
    }
}

__global__ void __launch_bounds__(256) reduce_xdbl() {
    int idx = blockIdx.x * 256 + threadIdx.x;   // BL*XP
    float s = 0.f;
    #pragma unroll
    for (int k = 0; k < KS; k++) s += g_part[(size_t)k * BL * XP + idx];
    g_xdbl[idx] = s;
}

// ---------------- selective scan (fused: scan + D-skip + SiLU(z) gate) ----------------
// block: 256 threads = 64 channels x 4 state-groups, one batch; grid (DI/64, BB)
__global__ void __launch_bounds__(256) scan_kernel(const float* __restrict__ A_log,
                                                   const float* __restrict__ Dskip) {
    const int b  = blockIdx.y;
    const int d0 = blockIdx.x * 64;
    const int tid = threadIdx.x;
    const int dl = tid >> 2;
    const int ng = tid & 3;
    const int d  = d0 + dl;

    __shared__ float sd[32][64], su[32][64], sB[32][16], sC[32][16], sy[32][64];

    const float LOG2E = 1.4426950408889634f;
    float A2[4], h[4];
    #pragma unroll
    for (int j = 0; j < 4; j++) {
        A2[j] = -__expf(A_log[d * DS + ng * 4 + j]) * LOG2E;
        h[j] = 0.f;
    }
    const float Dv = Dskip[d];

    for (int t0 = 0; t0 < LL; t0 += 32) {
        // stage delta/u (32x64 each) and B/C (32x16 each)
        #pragma unroll
        for (int q = 0; q < 8; q++) {
            int e = tid + q * 256;
            int i = e >> 6, c = e & 63;
            size_t g = (size_t)(b * LL + t0 + i) * DI + d0 + c;
            sd[i][c] = g_delta[g];
            su[i][c] = g_xc[g];
        }
        #pragma unroll
        for (int q = 0; q < 2; q++) {
            int e = tid + q * 256;
            int i = e >> 4, n = e & 15;
            size_t g = (size_t)(b * LL + t0 + i) * XP;
            sB[i][n] = g_xdbl[g + DR + n];
            sC[i][n] = g_xdbl[g + DR + DS + n];
        }
        __syncthreads();

        #pragma unroll 4
        for (int i = 0; i < 32; i++) {
            float dlt = sd[i][dl];
            float uu  = su[i][dl];
            float du  = dlt * uu;
            float p = 0.f;
            #pragma unroll
            for (int j = 0; j < 4; j++) {
                float dA = ex2f(dlt * A2[j]);
                h[j] = dA * h[j] + du * sB[i][ng * 4 + j];
                p += h[j] * sC[i][ng * 4 + j];
            }
            p += __shfl_xor_sync(0xffffffffu, p, 1);
            p += __shfl_xor_sync(0xffffffffu, p, 2);
            if (ng == 0) sy[i][dl] = p + uu * Dv;
        }
        __syncthreads();

        // gated coalesced writeback: y = scan * silu(z)
        #pragma unroll
        for (int q = 0; q < 8; q++) {
            int e = tid + q * 256;
            int i = e >> 6, c = e & 63;
            size_t r = (size_t)(b * LL + t0 + i);
            float z = g_xz[r * 2 * DI + DI + d0 + c];
            g_y[r * DI + d0 + c] = sy[i][c] * (z * sigmoidf_(z));
        }
        __syncthreads();
    }
}

// ---------------- masked pooling + classifier ----------------
__global__ void __launch_bounds__(256) pool_kernel(const int* __restrict__ mask) {
    int b  = blockIdx.y;
    int dm = blockIdx.x * 256 + threadIdx.x;
    float s = 0.f;
    #pragma unroll 8
    for (int t = 0; t < LL; t++) {
        s += g_h[(size_t)(b * LL + t) * DM + dm] * (float)mask[b * LL + t];
    }
    g_pool[b * DM + dm] = s;
}

__global__ void __launch_bounds__(256) fc_kernel(const int* __restrict__ mask,
                                                 const float* __restrict__ fcw,
                                                 const float* __restrict__ fcb,
                                                 float* __restrict__ out) {
    int b = blockIdx.x / 3, c = blockIdx.x % 3;
    float dot = 0.f;
    for (int k = threadIdx.x; k < DM; k += 256)
        dot += g_pool[b * DM + k] * fcw[c * DM + k];
    dot = block_sum256(dot);
    float ms = 0.f;
    for (int t = threadIdx.x; t < LL; t += 256)
        ms += (float)mask[b * LL + t];
    ms = block_sum256(ms);
    if (threadIdx.x == 0) out[b * 3 + c] = dot / ms + fcb[c];
}

// ---------------- launch ----------------
extern "C" void kernel_launch(void* const* d_in, const int* in_sizes, int n_in,
                              void* d_out, int out_size) {
    const float* emb      = (const float*)d_in[0];
    const float* norm_w   = (const float*)d_in[1];
    const float* in_proj  = (const float*)d_in[2];
    const float* conv_w   = (const float*)d_in[3];
    const float* conv_b   = (const float*)d_in[4];
    const float* x_proj   = (const float*)d_in[5];
    const float* dt_w     = (const float*)d_in[6];
    const float* dt_b     = (const float*)d_in[7];
    const float* A_log    = (const float*)d_in[8];
    const float* D_skip   = (const float*)d_in[9];
    const float* out_proj = (const float*)d_in[10];
    const float* norm_f   = (const float*)d_in[11];
    const float* fc_w     = (const float*)d_in[12];
    const float* fc_b     = (const float*)d_in[13];
    const int*   ids      = (const int*)d_in[14];
    const int*   mask     = (const int*)d_in[15];
    float* out = (float*)d_out;

    embed_kernel<<<(BL * DM / 4) / 256, 256>>>(emb, ids);

    for (int i = 0; i < NL; i++) {
        rmsnorm_kernel<<<BL, 256>>>(norm_w + (size_t)i * DM);
        gemm_tile<0><<<dim3(2 * DI / 128, BL / 128), 256>>>(
            in_proj + (size_t)i * 2 * DI * DM, nullptr);
        conv_silu_kernel<<<(BL * DI) / 256, 256>>>(
            conv_w + (size_t)i * DI * DC, conv_b + (size_t)i * DI);
        gemm_xproj<<<dim3(XP / 64, BL / 128, KS), 256>>>(x_proj + (size_t)i * XP * DI);
        reduce_xdbl<<<(BL * XP) / 256, 256>>>();
        gemm_tile<1><<<dim3(DI / 128, BL / 128), 256>>>(
            dt_w + (size_t)i * DI * DR, dt_b + (size_t)i * DI);
        scan_kernel<<<dim3(DI / 64, BB), 256>>>(
            A_log + (size_t)i * DI * DS, D_skip + (size_t)i * DI);
        gemm_tile<2><<<dim3(DM / 128, BL / 128), 256>>>(
            out_proj + (size_t)i * DM * DI, nullptr);
    }

    rmsnorm_kernel<<<BL, 256>>>(norm_f);
    pool_kernel<<<dim3(DM / 256, BB), 256>>>(mask);
    fc_kernel<<<BB * 3, 256>>>(mask, fc_w, fc_b, out);
}

// round 5
// speedup vs baseline: 1.1707x; 1.1707x over previous
#include <cuda_runtime.h>
#include <cuda_bf16.h>
#include <math.h>

// ---------------- model constants ----------------
#define NL 2
#define DM 2560
#define DI 5120
#define DS 16
#define DC 4
#define DR 160
#define XP 192          // DR + 2*DS
#define BB 2
#define LL 512
#define BL 1024         // BB*LL
#define KS 8            // split-K factor for x_proj

// ---------------- scratch (device globals; no allocation) ----------------
__device__ float g_x[BL * DM];            // residual stream
__device__ float g_h[BL * DM];            // normed activations
__device__ float g_xz[(size_t)BL * 2 * DI];
__device__ float g_xc[BL * DI];           // conv+silu output (= u)
__device__ float g_delta[BL * DI];
__device__ float g_y[BL * DI];            // gated scan output
__device__ float g_xdbl[BL * XP];
__device__ float g_part[(size_t)KS * BL * XP];
__device__ float g_pool[BB * DM];

// ---------------- f32x2 packed helpers (Blackwell 2x fp32 path) ----------------
typedef unsigned long long ull;
__device__ __forceinline__ ull dup2(float a) {
    ull r; asm("mov.b64 %0, {%1, %1};" : "=l"(r) : "f"(a)); return r;
}
__device__ __forceinline__ ull fma2_(ull a, ull b, ull c) {
    ull d; asm("fma.rn.f32x2 %0, %1, %2, %3;" : "=l"(d) : "l"(a), "l"(b), "l"(c)); return d;
}
__device__ __forceinline__ float2 unpack2(ull v) {
    float2 r; asm("mov.b64 {%0, %1}, %2;" : "=f"(r.x), "=f"(r.y) : "l"(v)); return r;
}

__device__ __forceinline__ float ex2f(float x) {
    float r; asm("ex2.approx.f32 %0, %1;" : "=f"(r) : "f"(x)); return r;
}
__device__ __forceinline__ float sigmoidf_(float x) {
    return 1.f / (1.f + __expf(-x));
}

__device__ __forceinline__ float block_sum256(float v) {
    __shared__ float sh[8];
    #pragma unroll
    for (int o = 16; o > 0; o >>= 1) v += __shfl_xor_sync(0xffffffffu, v, o);
    __syncthreads();                 // protect sh reuse across calls
    if ((threadIdx.x & 31) == 0) sh[threadIdx.x >> 5] = v;
    __syncthreads();
    v = sh[threadIdx.x & 7];
    #pragma unroll
    for (int o = 4; o > 0; o >>= 1) v += __shfl_xor_sync(0xffffffffu, v, o);
    return v;
}

// ---------------- embedding gather ----------------
__global__ void __launch_bounds__(256) embed_kernel(const float* __restrict__ emb,
                                                    const int* __restrict__ ids) {
    int idx = blockIdx.x * 256 + threadIdx.x;     // float4 units, total BL*DM/4
    int row = idx / (DM / 4);
    int c   = idx % (DM / 4);
    int id  = ids[row];
    ((float4*)g_x)[idx] = ((const float4*)(emb + (size_t)id * DM))[c];
}

// ---------------- rmsnorm: g_x -> g_h ----------------
__global__ void __launch_bounds__(256) rmsnorm_kernel(const float* __restrict__ w) {
    int row = blockIdx.x;
    const float* xr = g_x + (size_t)row * DM;
    float s = 0.f;
    #pragma unroll
    for (int q = 0; q < DM / 256; q++) {
        float v = xr[threadIdx.x + q * 256];
        s += v * v;
    }
    float tot = block_sum256(s);
    float inv = rsqrtf(tot * (1.f / DM) + 1e-5f);
    float* o = g_h + (size_t)row * DM;
    #pragma unroll
    for (int q = 0; q < DM / 256; q++) {
        int k = threadIdx.x + q * 256;
        o[k] = xr[k] * inv * w[k];
    }
}

// ---------------- 128x128x16 SGEMM (NT), 8x8 microtile, FFMA2 (f32x2) ----------------
// MODE 0: g_h  @ in_proj^T  -> g_xz     (K=DM,  lda=DM,  ldc=2*DI, plain store)
// MODE 1: g_xdbl[:, :160] @ dt_proj^T -> g_delta (K=DR, lda=XP, ldc=DI, softplus(.+bias))
// MODE 2: g_y  @ out_proj^T -> g_x     (K=DI,  lda=DI,  ldc=DM,  residual +=)
template <int MODE>
__global__ void __launch_bounds__(256, 2) gemm_tile(const float* __restrict__ W,
                                                    const float* __restrict__ bias) {
    constexpr int K   = (MODE == 0) ? DM : (MODE == 1) ? DR : DI;
    constexpr int LDA = (MODE == 0) ? DM : (MODE == 1) ? XP : DI;
    constexpr int LDC = (MODE == 0) ? 2 * DI : (MODE == 1) ? DI : DM;
    const float* __restrict__ A = (MODE == 0) ? g_h : (MODE == 1) ? g_xdbl : g_y;
    float* __restrict__ C       = (MODE == 0) ? g_xz : (MODE == 1) ? g_delta : g_x;

    __shared__ float As[16][132];
    __shared__ float Bs[16][132];
    const int bm  = blockIdx.y * 128;
    const int bn  = blockIdx.x * 128;
    const int tid = threadIdx.x;
    const int tx  = tid & 15;
    const int ty  = tid >> 4;
    const int lr  = tid >> 2;
    const int lc  = (tid & 3) * 4;

    ull acc[8][4];                        // 8 rows x 4 col-pairs (8 cols)
    #pragma unroll
    for (int i = 0; i < 8; i++)
        #pragma unroll
        for (int j = 0; j < 4; j++) acc[i][j] = 0ull;

    // prefetch first K-tile into registers
    float4 va[2], vb[2];
    #pragma unroll
    for (int rr = 0; rr < 2; rr++) {
        va[rr] = *(const float4*)&A[(size_t)(bm + lr + rr * 64) * LDA + lc];
        vb[rr] = *(const float4*)&W[(size_t)(bn + lr + rr * 64) * K + lc];
    }

    for (int k0 = 0; k0 < K; k0 += 16) {
        // store staged regs to smem
        #pragma unroll
        for (int rr = 0; rr < 2; rr++) {
            As[lc + 0][lr + rr * 64] = va[rr].x; As[lc + 1][lr + rr * 64] = va[rr].y;
            As[lc + 2][lr + rr * 64] = va[rr].z; As[lc + 3][lr + rr * 64] = va[rr].w;
            Bs[lc + 0][lr + rr * 64] = vb[rr].x; Bs[lc + 1][lr + rr * 64] = vb[rr].y;
            Bs[lc + 2][lr + rr * 64] = vb[rr].z; Bs[lc + 3][lr + rr * 64] = vb[rr].w;
        }
        __syncthreads();

        // prefetch next tile (wraps to 0 on the last iter; wasted but harmless)
        const int kn = (k0 + 16 < K) ? (k0 + 16) : 0;
        #pragma unroll
        for (int rr = 0; rr < 2; rr++) {
            va[rr] = *(const float4*)&A[(size_t)(bm + lr + rr * 64) * LDA + kn + lc];
            vb[rr] = *(const float4*)&W[(size_t)(bn + lr + rr * 64) * K + kn + lc];
        }

        #pragma unroll
        for (int k = 0; k < 16; k++) {
            float4 a0 = *(const float4*)&As[k][ty * 8];
            float4 a1 = *(const float4*)&As[k][ty * 8 + 4];
            const ull* bp = (const ull*)&Bs[k][tx * 8];
            ull b2[4] = {bp[0], bp[1], bp[2], bp[3]};
            float ar[8] = {a0.x, a0.y, a0.z, a0.w, a1.x, a1.y, a1.z, a1.w};
            #pragma unroll
            for (int i = 0; i < 8; i++) {
                ull af = dup2(ar[i]);
                #pragma unroll
                for (int jp = 0; jp < 4; jp++)
                    acc[i][jp] = fma2_(af, b2[jp], acc[i][jp]);
            }
        }
        __syncthreads();
    }

    #pragma unroll
    for (int i = 0; i < 8; i++) {
        size_t row = bm + ty * 8 + i;
        #pragma unroll
        for (int jj = 0; jj < 2; jj++) {
            int col = bn + tx * 8 + jj * 4;
            float2 p0 = unpack2(acc[i][jj * 2 + 0]);
            float2 p1 = unpack2(acc[i][jj * 2 + 1]);
            float v0 = p0.x, v1 = p0.y, v2 = p1.x, v3 = p1.y;
            float* cp = &C[row * LDC + col];
            if (MODE == 1) {
                v0 += bias[col + 0]; v1 += bias[col + 1];
                v2 += bias[col + 2]; v3 += bias[col + 3];
                v0 = (v0 > 20.f) ? v0 : log1pf(__expf(v0));
                v1 = (v1 > 20.f) ? v1 : log1pf(__expf(v1));
                v2 = (v2 > 20.f) ? v2 : log1pf(__expf(v2));
                v3 = (v3 > 20.f) ? v3 : log1pf(__expf(v3));
            }
            if (MODE == 2) {
                float4 o = *(const float4*)cp;
                v0 += o.x; v1 += o.y; v2 += o.z; v3 += o.w;
            }
            *(float4*)cp = make_float4(v0, v1, v2, v3);
        }
    }
}

// ---------------- depthwise causal conv1d + SiLU : g_xz[:, :DI] -> g_xc ----------------
__global__ void __launch_bounds__(256) conv_silu_kernel(const float* __restrict__ cw,
                                                        const float* __restrict__ cb) {
    int idx = blockIdx.x * 256 + threadIdx.x;   // over BL*DI
    int d = idx % DI;
    int r = idx / DI;                            // b*L + t
    int t = r & (LL - 1);
    float4 wv4 = ((const float4*)cw)[d];
    float wv[4] = {wv4.x, wv4.y, wv4.z, wv4.w};
    float acc = cb[d];
    if (t >= 3) {
        acc += wv[0] * g_xz[(size_t)(r - 3) * 2 * DI + d]
             + wv[1] * g_xz[(size_t)(r - 2) * 2 * DI + d]
             + wv[2] * g_xz[(size_t)(r - 1) * 2 * DI + d]
             + wv[3] * g_xz[(size_t)(r    ) * 2 * DI + d];
    } else {
        #pragma unroll
        for (int k = 0; k < 4; k++) {
            int tt = t - 3 + k;
            if (tt >= 0) acc += wv[k] * g_xz[(size_t)(r - 3 + k) * 2 * DI + d];
        }
    }
    g_xc[idx] = acc * sigmoidf_(acc);
}

// ---------------- x_proj split-K: g_xc @ x_proj^T -> g_part (FFMA2) ----------------
__global__ void __launch_bounds__(256, 2) gemm_xproj(const float* __restrict__ W) {
    __shared__ float As[16][132];
    __shared__ float Bs[16][68];
    const int bn  = blockIdx.x * 64;   // 0..2
    const int bm  = blockIdx.y * 128;  // 0..7
    const int ks  = blockIdx.z;        // 0..7
    const int tid = threadIdx.x;
    const int tx  = tid & 15;
    const int ty  = tid >> 4;
    const int lr  = tid >> 2;
    const int lc  = (tid & 3) * 4;

    ull acc[8][2];
    #pragma unroll
    for (int i = 0; i < 8; i++) { acc[i][0] = 0ull; acc[i][1] = 0ull; }

    const int kb = ks * (DI / KS);

    float4 va[2], vb;
    #pragma unroll
    for (int rr = 0; rr < 2; rr++)
        va[rr] = *(const float4*)&g_xc[(size_t)(bm + lr + rr * 64) * DI + kb + lc];
    vb = *(const float4*)&W[(size_t)(bn + lr) * DI + kb + lc];

    for (int k0 = kb; k0 < kb + DI / KS; k0 += 16) {
        #pragma unroll
        for (int rr = 0; rr < 2; rr++) {
            As[lc + 0][lr + rr * 64] = va[rr].x; As[lc + 1][lr + rr * 64] = va[rr].y;
            As[lc + 2][lr + rr * 64] = va[rr].z; As[lc + 3][lr + rr * 64] = va[rr].w;
        }
        Bs[lc + 0][lr] = vb.x; Bs[lc + 1][lr] = vb.y;
        Bs[lc + 2][lr] = vb.z; Bs[lc + 3][lr] = vb.w;
        __syncthreads();

        const int kn = (k0 + 16 < kb + DI / KS) ? (k0 + 16) : kb;
        #pragma unroll
        for (int rr = 0; rr < 2; rr++)
            va[rr] = *(const float4*)&g_xc[(size_t)(bm + lr + rr * 64) * DI + kn + lc];
        vb = *(const float4*)&W[(size_t)(bn + lr) * DI + kn + lc];

        #pragma unroll
        for (int k = 0; k < 16; k++) {
            float4 a0 = *(const float4*)&As[k][ty * 8];
            float4 a1 = *(const float4*)&As[k][ty * 8 + 4];
            const ull* bp = (const ull*)&Bs[k][tx * 4];
            ull b2[2] = {bp[0], bp[1]};
            float ar[8] = {a0.x, a0.y, a0.z, a0.w, a1.x, a1.y, a1.z, a1.w};
            #pragma unroll
            for (int i = 0; i < 8; i++) {
                ull af = dup2(ar[i]);
                acc[i][0] = fma2_(af, b2[0], acc[i][0]);
                acc[i][1] = fma2_(af, b2[1], acc[i][1]);
            }
        }
        __syncthreads();
    }
    #pragma unroll
    for (int i = 0; i < 8; i++) {
        float2 p0 = unpack2(acc[i][0]);
        float2 p1 = unpack2(acc[i][1]);
        *(float4*)&g_part[((size_t)ks * BL + bm + ty * 8 + i) * XP + bn + tx * 4] =
            make_float4(p0.x, p0.y, p1.x, p1.y);
    }
}

__global__ void __launch_bounds__(256) reduce_xdbl() {
    int idx = blockIdx.x * 256 + threadIdx.x;   // BL*XP
    float s = 0.f;
    #pragma unroll
    for (int k = 0; k < KS; k++) s += g_part[(size_t)k * BL * XP + idx];
    g_xdbl[idx] = s;
}

// ---------------- selective scan (fused: scan + D-skip + SiLU(z) gate) ----------------
// block: 256 threads = 64 channels x 4 state-groups, one batch; grid (DI/64, BB)
__global__ void __launch_bounds__(256) scan_kernel(const float* __restrict__ A_log,
                                                   const float* __restrict__ Dskip) {
    const int b  = blockIdx.y;
    const int d0 = blockIdx.x * 64;
    const int tid = threadIdx.x;
    const int dl = tid >> 2;
    const int ng = tid & 3;
    const int d  = d0 + dl;

    __shared__ float sd[32][64], su[32][64], sB[32][16], sC[32][16], sy[32][64];

    const float LOG2E = 1.4426950408889634f;
    float A2[4], h[4];
    #pragma unroll
    for (int j = 0; j < 4; j++) {
        A2[j] = -__expf(A_log[d * DS + ng * 4 + j]) * LOG2E;
        h[j] = 0.f;
    }
    const float Dv = Dskip[d];

    for (int t0 = 0; t0 < LL; t0 += 32) {
        // stage delta/u (32x64 each) and B/C (32x16 each)
        #pragma unroll
        for (int q = 0; q < 8; q++) {
            int e = tid + q * 256;
            int i = e >> 6, c = e & 63;
            size_t g = (size_t)(b * LL + t0 + i) * DI + d0 + c;
            sd[i][c] = g_delta[g];
            su[i][c] = g_xc[g];
        }
        #pragma unroll
        for (int q = 0; q < 2; q++) {
            int e = tid + q * 256;
            int i = e >> 4, n = e & 15;
            size_t g = (size_t)(b * LL + t0 + i) * XP;
            sB[i][n] = g_xdbl[g + DR + n];
            sC[i][n] = g_xdbl[g + DR + DS + n];
        }
        __syncthreads();

        #pragma unroll 4
        for (int i = 0; i < 32; i++) {
            float dlt = sd[i][dl];
            float uu  = su[i][dl];
            float du  = dlt * uu;
            float p = 0.f;
            #pragma unroll
            for (int j = 0; j < 4; j++) {
                float dA = ex2f(dlt * A2[j]);
                h[j] = dA * h[j] + du * sB[i][ng * 4 + j];
                p += h[j] * sC[i][ng * 4 + j];
            }
            p += __shfl_xor_sync(0xffffffffu, p, 1);
            p += __shfl_xor_sync(0xffffffffu, p, 2);
            if (ng == 0) sy[i][dl] = p + uu * Dv;
        }
        __syncthreads();

        // gated coalesced writeback: y = scan * silu(z)
        #pragma unroll
        for (int q = 0; q < 8; q++) {
            int e = tid + q * 256;
            int i = e >> 6, c = e & 63;
            size_t r = (size_t)(b * LL + t0 + i);
            float z = g_xz[r * 2 * DI + DI + d0 + c];
            g_y[r * DI + d0 + c] = sy[i][c] * (z * sigmoidf_(z));
        }
        __syncthreads();
    }
}

// ---------------- masked pooling + classifier ----------------
__global__ void __launch_bounds__(256) pool_kernel(const int* __restrict__ mask) {
    int b  = blockIdx.y;
    int dm = blockIdx.x * 256 + threadIdx.x;
    float s = 0.f;
    #pragma unroll 8
    for (int t = 0; t < LL; t++) {
        s += g_h[(size_t)(b * LL + t) * DM + dm] * (float)mask[b * LL + t];
    }
    g_pool[b * DM + dm] = s;
}

__global__ void __launch_bounds__(256) fc_kernel(const int* __restrict__ mask,
                                                 const float* __restrict__ fcw,
                                                 const float* __restrict__ fcb,
                                                 float* __restrict__ out) {
    int b = blockIdx.x / 3, c = blockIdx.x % 3;
    float dot = 0.f;
    for (int k = threadIdx.x; k < DM; k += 256)
        dot += g_pool[b * DM + k] * fcw[c * DM + k];
    dot = block_sum256(dot);
    float ms = 0.f;
    for (int t = threadIdx.x; t < LL; t += 256)
        ms += (float)mask[b * LL + t];
    ms = block_sum256(ms);
    if (threadIdx.x == 0) out[b * 3 + c] = dot / ms + fcb[c];
}

// ---------------- launch ----------------
extern "C" void kernel_launch(void* const* d_in, const int* in_sizes, int n_in,
                              void* d_out, int out_size) {
    const float* emb      = (const float*)d_in[0];
    const float* norm_w   = (const float*)d_in[1];
    const float* in_proj  = (const float*)d_in[2];
    const float* conv_w   = (const float*)d_in[3];
    const float* conv_b   = (const float*)d_in[4];
    const float* x_proj   = (const float*)d_in[5];
    const float* dt_w     = (const float*)d_in[6];
    const float* dt_b     = (const float*)d_in[7];
    const float* A_log    = (const float*)d_in[8];
    const float* D_skip   = (const float*)d_in[9];
    const float* out_proj = (const float*)d_in[10];
    const float* norm_f   = (const float*)d_in[11];
    const float* fc_w     = (const float*)d_in[12];
    const float* fc_b     = (const float*)d_in[13];
    const int*   ids      = (const int*)d_in[14];
    const int*   mask     = (const int*)d_in[15];
    float* out = (float*)d_out;

    embed_kernel<<<(BL * DM / 4) / 256, 256>>>(emb, ids);

    for (int i = 0; i < NL; i++) {
        rmsnorm_kernel<<<BL, 256>>>(norm_w + (size_t)i * DM);
        gemm_tile<0><<<dim3(2 * DI / 128, BL / 128), 256>>>(
            in_proj + (size_t)i * 2 * DI * DM, nullptr);
        conv_silu_kernel<<<(BL * DI) / 256, 256>>>(
            conv_w + (size_t)i * DI * DC, conv_b + (size_t)i * DI);
        gemm_xproj<<<dim3(XP / 64, BL / 128, KS), 256>>>(x_proj + (size_t)i * XP * DI);
        reduce_xdbl<<<(BL * XP) / 256, 256>>>();
        gemm_tile<1><<<dim3(DI / 128, BL / 128), 256>>>(
            dt_w + (size_t)i * DI * DR, dt_b + (size_t)i * DI);
        scan_kernel<<<dim3(DI / 64, BB), 256>>>(
            A_log + (size_t)i * DI * DS, D_skip + (size_t)i * DI);
        gemm_tile<2><<<dim3(DM / 128, BL / 128), 256>>>(
            out_proj + (size_t)i * DM * DI, nullptr);
    }

    rmsnorm_kernel<<<BL, 256>>>(norm_f);
    pool_kernel<<<dim3(DM / 256, BB), 256>>>(mask);
    fc_kernel<<<BB * 3, 256>>>(mask, fc_w, fc_b, out);
}

// round 15
// speedup vs baseline: 2.0667x; 1.7654x over previous
#include <cuda_runtime.h>
#include <cuda_bf16.h>
#include <math.h>
#include <stdint.h>

// ---------------- model constants ----------------
#define NL 2
#define DM 2560
#define DI 5120
#define DS 16
#define DC 4
#define DR 160
#define XP 192          // DR + 2*DS
#define BB 2
#define LL 512
#define BL 1024         // BB*LL
#define KS 8            // split-K factor for x_proj

// ---------------- scratch (device globals; no allocation) ----------------
__device__ float g_x[BL * DM];            // residual stream
__device__ float g_h[BL * DM];            // normed activations
__device__ float g_xz[(size_t)BL * 2 * DI];
__device__ float g_xc[BL * DI];           // conv+silu output (= u)
__device__ float g_delta[BL * DI];
__device__ float g_y[BL * DI];            // gated scan output
__device__ float g_xdbl[BL * XP];
__device__ float g_part[(size_t)KS * BL * XP];
__device__ float g_pool[BB * DM];
// bf16 3-term split operands: A' = [Ah|Al|Ah] (M x 3K), W' = [Wh|Wh|Wl] (N x 3K)
__device__ __nv_bfloat16 g_asplit[(size_t)BL * 3 * DI];
__device__ __nv_bfloat16 g_wsplit[(size_t)(2 * DI) * 3 * DM];

// ---------------- f32x2 packed helpers ----------------
typedef unsigned long long ull;
__device__ __forceinline__ ull dup2(float a) {
    ull r; asm("mov.b64 %0, {%1, %1};" : "=l"(r) : "f"(a)); return r;
}
__device__ __forceinline__ ull fma2_(ull a, ull b, ull c) {
    ull d; asm("fma.rn.f32x2 %0, %1, %2, %3;" : "=l"(d) : "l"(a), "l"(b), "l"(c)); return d;
}
__device__ __forceinline__ float2 unpack2(ull v) {
    float2 r; asm("mov.b64 {%0, %1}, %2;" : "=f"(r.x), "=f"(r.y) : "l"(v)); return r;
}

__device__ __forceinline__ float ex2f(float x) {
    float r; asm("ex2.approx.f32 %0, %1;" : "=f"(r) : "f"(x)); return r;
}
__device__ __forceinline__ float sigmoidf_(float x) {
    return 1.f / (1.f + __expf(-x));
}

// ---------------- HMMA primitive (baseline PTX ISA) ----------------
__device__ __forceinline__ void mma16816(float* c, const uint32_t* a, const uint32_t* b) {
    asm volatile(
        "mma.sync.aligned.m16n8k16.row.col.f32.bf16.bf16.f32 "
        "{%0,%1,%2,%3}, {%4,%5,%6,%7}, {%8,%9}, {%0,%1,%2,%3};"
        : "+f"(c[0]), "+f"(c[1]), "+f"(c[2]), "+f"(c[3])
        : "r"(a[0]), "r"(a[1]), "r"(a[2]), "r"(a[3]), "r"(b[0]), "r"(b[1]));
}

__device__ __forceinline__ float block_sum256(float v) {
    __shared__ float sh[8];
    #pragma unroll
    for (int o = 16; o > 0; o >>= 1) v += __shfl_xor_sync(0xffffffffu, v, o);
    __syncthreads();
    if ((threadIdx.x & 31) == 0) sh[threadIdx.x >> 5] = v;
    __syncthreads();
    v = sh[threadIdx.x & 7];
    #pragma unroll
    for (int o = 4; o > 0; o >>= 1) v += __shfl_xor_sync(0xffffffffu, v, o);
    return v;
}

// ---------------- embedding gather ----------------
__global__ void __launch_bounds__(256) embed_kernel(const float* __restrict__ emb,
                                                    const int* __restrict__ ids) {
    int idx = blockIdx.x * 256 + threadIdx.x;
    int row = idx / (DM / 4);
    int c   = idx % (DM / 4);
    int id  = ids[row];
    ((float4*)g_x)[idx] = ((const float4*)(emb + (size_t)id * DM))[c];
}

// ---------------- rmsnorm: g_x -> g_h ----------------
__global__ void __launch_bounds__(256) rmsnorm_kernel(const float* __restrict__ w) {
    int row = blockIdx.x;
    const float* xr = g_x + (size_t)row * DM;
    float s = 0.f;
    #pragma unroll
    for (int q = 0; q < DM / 256; q++) {
        float v = xr[threadIdx.x + q * 256];
        s += v * v;
    }
    float tot = block_sum256(s);
    float inv = rsqrtf(tot * (1.f / DM) + 1e-5f);
    float* o = g_h + (size_t)row * DM;
    #pragma unroll
    for (int q = 0; q < DM / 256; q++) {
        int k = threadIdx.x + q * 256;
        o[k] = xr[k] * inv * w[k];
    }
}

// ---------------- bf16 3-term split conversions ----------------
// FIX (R13): source selected INSIDE device code via SRC template param.
// Passing __device__ globals (g_h/g_y) as host-side kernel args passed the
// HOST shadow address; GB300's ATS made the deref legal -> read zeros ->
// A' = 0 -> GEMMs output 0 -> identical rel_err across all hmma variants.
template <int K, int SRC>   // SRC 0: g_h, 1: g_y
__global__ void __launch_bounds__(256) split_a_kernel() {
    const float* __restrict__ src = (SRC == 0) ? g_h : g_y;
    int idx = blockIdx.x * 256 + threadIdx.x;          // over BL*K/2
    int k2 = idx % (K / 2), m = idx / (K / 2);
    float2 v = *(const float2*)&src[(size_t)m * K + 2 * k2];
    __nv_bfloat16 h0 = __float2bfloat16(v.x), h1 = __float2bfloat16(v.y);
    __nv_bfloat162 hi; hi.x = h0; hi.y = h1;
    __nv_bfloat162 lo;
    lo.x = __float2bfloat16(v.x - __bfloat162float(h0));
    lo.y = __float2bfloat16(v.y - __bfloat162float(h1));
    __nv_bfloat162* dst = (__nv_bfloat162*)(g_asplit + (size_t)m * 3 * K);
    dst[k2] = hi; dst[K / 2 + k2] = lo; dst[K + k2] = hi;
}

template <int K>
__global__ void __launch_bounds__(256) split_w_kernel(const float* __restrict__ W) {
    int idx = blockIdx.x * 256 + threadIdx.x;          // over N*K/2
    int k2 = idx % (K / 2), n = idx / (K / 2);
    float2 v = *(const float2*)&W[(size_t)n * K + 2 * k2];
    __nv_bfloat16 h0 = __float2bfloat16(v.x), h1 = __float2bfloat16(v.y);
    __nv_bfloat162 hi; hi.x = h0; hi.y = h1;
    __nv_bfloat162 lo;
    lo.x = __float2bfloat16(v.x - __bfloat162float(h0));
    lo.y = __float2bfloat16(v.y - __bfloat162float(h1));
    __nv_bfloat162* dst = (__nv_bfloat162*)(g_wsplit + (size_t)n * 3 * K);
    dst[k2] = hi; dst[K / 2 + k2] = hi; dst[K + k2] = lo;
}

// ---------------- HMMA bf16 GEMM: C[M,N] = A'[M,K'] @ W'[N,K']^T ----------------
// 128x128 CTA, 8 warps = 2(M) x 4(N), warp tile 64x32, K-chunk 64 bf16.
// STATIC shared (36864B), single-buffered with register prefetch.
// Padded pitch 144B: fragment LDS word-bank = 4*gid + tig -> conflict-free.
// MODE 0: -> g_xz (NT=10240, K'=7680, plain store)
// MODE 2: -> g_x  (NT=2560,  K'=15360, residual +=)
#define PA 144
#define TILEB (128 * PA)           // 18432 per operand tile

template <int MODE>
__global__ void __launch_bounds__(256) hmma_gemm() {
    constexpr int NT = (MODE == 0) ? 2 * DI : DM;
    constexpr int KP = (MODE == 0) ? 3 * DM : 3 * DI;
    constexpr int T  = KP / 64;
    float* __restrict__ C = (MODE == 0) ? g_xz : g_x;

    __shared__ __align__(16) char smem[2 * TILEB];     // 36864 bytes, static
    const int bm = blockIdx.x * 128, bn = blockIdx.y * 128;
    const int tid = threadIdx.x, lane = tid & 31, wid = tid >> 5;
    const int wm = wid & 1, wn = wid >> 1;
    const int gid = lane >> 2, tig = lane & 3;

    const __nv_bfloat16* __restrict__ gA = g_asplit;
    const __nv_bfloat16* __restrict__ gB = g_wsplit;

    float acc[4][4][4];
    #pragma unroll
    for (int i = 0; i < 4; i++)
        #pragma unroll
        for (int j = 0; j < 4; j++)
            #pragma unroll
            for (int v = 0; v < 4; v++) acc[i][j][v] = 0.f;

    uint4 ra[4], rb[4];

    auto gload = [&](int t) {
        const int k0 = t * 64;
        #pragma unroll
        for (int q = 0; q < 4; q++) {
            int e = tid + q * 256;            // 0..1023 = 128 rows x 8 x 16B
            int row = e >> 3, cb = e & 7;
            ra[q] = *(const uint4*)(gA + (size_t)(bm + row) * KP + k0 + cb * 8);
            rb[q] = *(const uint4*)(gB + (size_t)(bn + row) * KP + k0 + cb * 8);
        }
    };
    auto sts = [&]() {
        char* Ab = smem;
        char* Bb = smem + TILEB;
        #pragma unroll
        for (int q = 0; q < 4; q++) {
            int e = tid + q * 256;
            int row = e >> 3, cb = e & 7;
            int off = row * PA + cb * 16;
            *(uint4*)(Ab + off) = ra[q];
            *(uint4*)(Bb + off) = rb[q];
        }
    };

    gload(0); sts();
    __syncthreads();

    for (int t = 0; t < T; t++) {
        if (t + 1 < T) gload(t + 1);

        const char* Ab = smem;
        const char* Bb = smem + TILEB;
        #pragma unroll
        for (int kk = 0; kk < 4; kk++) {
            // a-frag: A[gid][2tig..], A[gid+8][..], A[gid][2tig+8..], A[gid+8][2tig+8..]
            uint32_t a[4][4];
            #pragma unroll
            for (int i = 0; i < 4; i++) {
                const char* p = Ab + (wm * 64 + i * 16 + gid) * PA + kk * 32 + tig * 4;
                a[i][0] = *(const uint32_t*)(p);
                a[i][1] = *(const uint32_t*)(p + 8 * PA);
                a[i][2] = *(const uint32_t*)(p + 16);
                a[i][3] = *(const uint32_t*)(p + 8 * PA + 16);
            }
            // b-frag (NT): b0 = W[n=gid][k=2tig..+1], b1 = +8 in k
            uint32_t b[4][2];
            #pragma unroll
            for (int j = 0; j < 4; j++) {
                const char* p = Bb + (wn * 32 + j * 8 + gid) * PA + kk * 32 + tig * 4;
                b[j][0] = *(const uint32_t*)(p);
                b[j][1] = *(const uint32_t*)(p + 16);
            }
            #pragma unroll
            for (int i = 0; i < 4; i++)
                #pragma unroll
                for (int j = 0; j < 4; j++)
                    mma16816(acc[i][j], a[i], b[j]);
        }

        if (t + 1 < T) {
            __syncthreads();     // all warps done reading this chunk
            sts();               // overwrite with next chunk
            __syncthreads();     // next chunk visible
        }
    }

    // epilogue: c-frag rows gid/gid+8, cols 2tig..+1
    #pragma unroll
    for (int i = 0; i < 4; i++) {
        #pragma unroll
        for (int j = 0; j < 4; j++) {
            int r0 = bm + wm * 64 + i * 16 + gid;
            int c0 = bn + wn * 32 + j * 8 + tig * 2;
            float* p0 = &C[(size_t)r0 * NT + c0];
            float* p1 = &C[(size_t)(r0 + 8) * NT + c0];
            float v0 = acc[i][j][0], v1 = acc[i][j][1];
            float v2 = acc[i][j][2], v3 = acc[i][j][3];
            if (MODE == 2) {
                float2 o0 = *(const float2*)p0;
                float2 o1 = *(const float2*)p1;
                v0 += o0.x; v1 += o0.y; v2 += o1.x; v3 += o1.y;
            }
            *(float2*)p0 = make_float2(v0, v1);
            *(float2*)p1 = make_float2(v2, v3);
        }
    }
}

// ---------------- FFMA2 SGEMM for dt_proj (softplus epilogue) ----------------
template <int MODE>
__global__ void __launch_bounds__(256, 2) gemm_tile(const float* __restrict__ W,
                                                    const float* __restrict__ bias) {
    constexpr int K   = DR;
    constexpr int LDA = XP;
    constexpr int LDC = DI;
    const float* __restrict__ A = g_xdbl;
    float* __restrict__ C       = g_delta;

    __shared__ float As[16][132];
    __shared__ float Bs[16][132];
    const int bm  = blockIdx.y * 128;
    const int bn  = blockIdx.x * 128;
    const int tid = threadIdx.x;
    const int tx  = tid & 15;
    const int ty  = tid >> 4;
    const int lr  = tid >> 2;
    const int lc  = (tid & 3) * 4;

    ull acc[8][4];
    #pragma unroll
    for (int i = 0; i < 8; i++)
        #pragma unroll
        for (int j = 0; j < 4; j++) acc[i][j] = 0ull;

    float4 va[2], vb[2];
    #pragma unroll
    for (int rr = 0; rr < 2; rr++) {
        va[rr] = *(const float4*)&A[(size_t)(bm + lr + rr * 64) * LDA + lc];
        vb[rr] = *(const float4*)&W[(size_t)(bn + lr + rr * 64) * K + lc];
    }

    for (int k0 = 0; k0 < K; k0 += 16) {
        #pragma unroll
        for (int rr = 0; rr < 2; rr++) {
            As[lc + 0][lr + rr * 64] = va[rr].x; As[lc + 1][lr + rr * 64] = va[rr].y;
            As[lc + 2][lr + rr * 64] = va[rr].z; As[lc + 3][lr + rr * 64] = va[rr].w;
            Bs[lc + 0][lr + rr * 64] = vb[rr].x; Bs[lc + 1][lr + rr * 64] = vb[rr].y;
            Bs[lc + 2][lr + rr * 64] = vb[rr].z; Bs[lc + 3][lr + rr * 64] = vb[rr].w;
        }
        __syncthreads();

        const int kn = (k0 + 16 < K) ? (k0 + 16) : 0;
        #pragma unroll
        for (int rr = 0; rr < 2; rr++) {
            va[rr] = *(const float4*)&A[(size_t)(bm + lr + rr * 64) * LDA + kn + lc];
            vb[rr] = *(const float4*)&W[(size_t)(bn + lr + rr * 64) * K + kn + lc];
        }

        #pragma unroll
        for (int k = 0; k < 16; k++) {
            float4 a0 = *(const float4*)&As[k][ty * 8];
            float4 a1 = *(const float4*)&As[k][ty * 8 + 4];
            const ull* bp = (const ull*)&Bs[k][tx * 8];
            ull b2[4] = {bp[0], bp[1], bp[2], bp[3]};
            float ar[8] = {a0.x, a0.y, a0.z, a0.w, a1.x, a1.y, a1.z, a1.w};
            #pragma unroll
            for (int i = 0; i < 8; i++) {
                ull af = dup2(ar[i]);
                #pragma unroll
                for (int jp = 0; jp < 4; jp++)
                    acc[i][jp] = fma2_(af, b2[jp], acc[i][jp]);
            }
        }
        __syncthreads();
    }

    #pragma unroll
    for (int i = 0; i < 8; i++) {
        size_t row = bm + ty * 8 + i;
        #pragma unroll
        for (int jj = 0; jj < 2; jj++) {
            int col = bn + tx * 8 + jj * 4;
            float2 p0 = unpack2(acc[i][jj * 2 + 0]);
            float2 p1 = unpack2(acc[i][jj * 2 + 1]);
            float v0 = p0.x, v1 = p0.y, v2 = p1.x, v3 = p1.y;
            v0 += bias[col + 0]; v1 += bias[col + 1];
            v2 += bias[col + 2]; v3 += bias[col + 3];
            v0 = (v0 > 20.f) ? v0 : log1pf(__expf(v0));
            v1 = (v1 > 20.f) ? v1 : log1pf(__expf(v1));
            v2 = (v2 > 20.f) ? v2 : log1pf(__expf(v2));
            v3 = (v3 > 20.f) ? v3 : log1pf(__expf(v3));
            *(float4*)&C[row * LDC + col] = make_float4(v0, v1, v2, v3);
        }
    }
}

// ---------------- depthwise causal conv1d + SiLU ----------------
__global__ void __launch_bounds__(256) conv_silu_kernel(const float* __restrict__ cw,
                                                        const float* __restrict__ cb) {
    int idx = blockIdx.x * 256 + threadIdx.x;
    int d = idx % DI;
    int r = idx / DI;
    int t = r & (LL - 1);
    float4 wv4 = ((const float4*)cw)[d];
    float wv[4] = {wv4.x, wv4.y, wv4.z, wv4.w};
    float acc = cb[d];
    if (t >= 3) {
        acc += wv[0] * g_xz[(size_t)(r - 3) * 2 * DI + d]
             + wv[1] * g_xz[(size_t)(r - 2) * 2 * DI + d]
             + wv[2] * g_xz[(size_t)(r - 1) * 2 * DI + d]
             + wv[3] * g_xz[(size_t)(r    ) * 2 * DI + d];
    } else {
        #pragma unroll
        for (int k = 0; k < 4; k++) {
            int tt = t - 3 + k;
            if (tt >= 0) acc += wv[k] * g_xz[(size_t)(r - 3 + k) * 2 * DI + d];
        }
    }
    g_xc[idx] = acc * sigmoidf_(acc);
}

// ---------------- x_proj split-K (FFMA2) ----------------
__global__ void __launch_bounds__(256, 2) gemm_xproj(const float* __restrict__ W) {
    __shared__ float As[16][132];
    __shared__ float Bs[16][68];
    const int bn  = blockIdx.x * 64;
    const int bm  = blockIdx.y * 128;
    const int ks  = blockIdx.z;
    const int tid = threadIdx.x;
    const int tx  = tid & 15;
    const int ty  = tid >> 4;
    const int lr  = tid >> 2;
    const int lc  = (tid & 3) * 4;

    ull acc[8][2];
    #pragma unroll
    for (int i = 0; i < 8; i++) { acc[i][0] = 0ull; acc[i][1] = 0ull; }

    const int kb = ks * (DI / KS);

    float4 va[2], vb;
    #pragma unroll
    for (int rr = 0; rr < 2; rr++)
        va[rr] = *(const float4*)&g_xc[(size_t)(bm + lr + rr * 64) * DI + kb + lc];
    vb = *(const float4*)&W[(size_t)(bn + lr) * DI + kb + lc];

    for (int k0 = kb; k0 < kb + DI / KS; k0 += 16) {
        #pragma unroll
        for (int rr = 0; rr < 2; rr++) {
            As[lc + 0][lr + rr * 64] = va[rr].x; As[lc + 1][lr + rr * 64] = va[rr].y;
            As[lc + 2][lr + rr * 64] = va[rr].z; As[lc + 3][lr + rr * 64] = va[rr].w;
        }
        Bs[lc + 0][lr] = vb.x; Bs[lc + 1][lr] = vb.y;
        Bs[lc + 2][lr] = vb.z; Bs[lc + 3][lr] = vb.w;
        __syncthreads();

        const int kn = (k0 + 16 < kb + DI / KS) ? (k0 + 16) : kb;
        #pragma unroll
        for (int rr = 0; rr < 2; rr++)
            va[rr] = *(const float4*)&g_xc[(size_t)(bm + lr + rr * 64) * DI + kn + lc];
        vb = *(const float4*)&W[(size_t)(bn + lr) * DI + kn + lc];

        #pragma unroll
        for (int k = 0; k < 16; k++) {
            float4 a0 = *(const float4*)&As[k][ty * 8];
            float4 a1 = *(const float4*)&As[k][ty * 8 + 4];
            const ull* bp = (const ull*)&Bs[k][tx * 4];
            ull b2[2] = {bp[0], bp[1]};
            float ar[8] = {a0.x, a0.y, a0.z, a0.w, a1.x, a1.y, a1.z, a1.w};
            #pragma unroll
            for (int i = 0; i < 8; i++) {
                ull af = dup2(ar[i]);
                acc[i][0] = fma2_(af, b2[0], acc[i][0]);
                acc[i][1] = fma2_(af, b2[1], acc[i][1]);
            }
        }
        __syncthreads();
    }
    #pragma unroll
    for (int i = 0; i < 8; i++) {
        float2 p0 = unpack2(acc[i][0]);
        float2 p1 = unpack2(acc[i][1]);
        *(float4*)&g_part[((size_t)ks * BL + bm + ty * 8 + i) * XP + bn + tx * 4] =
            make_float4(p0.x, p0.y, p1.x, p1.y);
    }
}

__global__ void __launch_bounds__(256) reduce_xdbl() {
    int idx = blockIdx.x * 256 + threadIdx.x;
    float s = 0.f;
    #pragma unroll
    for (int k = 0; k < KS; k++) s += g_part[(size_t)k * BL * XP + idx];
    g_xdbl[idx] = s;
}

// ---------------- selective scan (fused gate) ----------------
__global__ void __launch_bounds__(256) scan_kernel(const float* __restrict__ A_log,
                                                   const float* __restrict__ Dskip) {
    const int b  = blockIdx.y;
    const int d0 = blockIdx.x * 64;
    const int tid = threadIdx.x;
    const int dl = tid >> 2;
    const int ng = tid & 3;
    const int d  = d0 + dl;

    __shared__ float sd[32][64], su[32][64], sB[32][16], sC[32][16], sy[32][64];

    const float LOG2E = 1.4426950408889634f;
    float A2[4], h[4];
    #pragma unroll
    for (int j = 0; j < 4; j++) {
        A2[j] = -__expf(A_log[d * DS + ng * 4 + j]) * LOG2E;
        h[j] = 0.f;
    }
    const float Dv = Dskip[d];

    for (int t0 = 0; t0 < LL; t0 += 32) {
        #pragma unroll
        for (int q = 0; q < 8; q++) {
            int e = tid + q * 256;
            int i = e >> 6, c = e & 63;
            size_t g = (size_t)(b * LL + t0 + i) * DI + d0 + c;
            sd[i][c] = g_delta[g];
            su[i][c] = g_xc[g];
        }
        #pragma unroll
        for (int q = 0; q < 2; q++) {
            int e = tid + q * 256;
            int i = e >> 4, n = e & 15;
            size_t g = (size_t)(b * LL + t0 + i) * XP;
            sB[i][n] = g_xdbl[g + DR + n];
            sC[i][n] = g_xdbl[g + DR + DS + n];
        }
        __syncthreads();

        #pragma unroll 4
        for (int i = 0; i < 32; i++) {
            float dlt = sd[i][dl];
            float uu  = su[i][dl];
            float du  = dlt * uu;
            float p = 0.f;
            #pragma unroll
            for (int j = 0; j < 4; j++) {
                float dA = ex2f(dlt * A2[j]);
                h[j] = dA * h[j] + du * sB[i][ng * 4 + j];
                p += h[j] * sC[i][ng * 4 + j];
            }
            p += __shfl_xor_sync(0xffffffffu, p, 1);
            p += __shfl_xor_sync(0xffffffffu, p, 2);
            if (ng == 0) sy[i][dl] = p + uu * Dv;
        }
        __syncthreads();

        #pragma unroll
        for (int q = 0; q < 8; q++) {
            int e = tid + q * 256;
            int i = e >> 6, c = e & 63;
            size_t r = (size_t)(b * LL + t0 + i);
            float z = g_xz[r * 2 * DI + DI + d0 + c];
            g_y[r * DI + d0 + c] = sy[i][c] * (z * sigmoidf_(z));
        }
        __syncthreads();
    }
}

// ---------------- masked pooling + classifier ----------------
__global__ void __launch_bounds__(256) pool_kernel(const int* __restrict__ mask) {
    int b  = blockIdx.y;
    int dm = blockIdx.x * 256 + threadIdx.x;
    float s = 0.f;
    #pragma unroll 8
    for (int t = 0; t < LL; t++) {
        s += g_h[(size_t)(b * LL + t) * DM + dm] * (float)mask[b * LL + t];
    }
    g_pool[b * DM + dm] = s;
}

__global__ void __launch_bounds__(256) fc_kernel(const int* __restrict__ mask,
                                                 const float* __restrict__ fcw,
                                                 const float* __restrict__ fcb,
                                                 float* __restrict__ out) {
    int b = blockIdx.x / 3, c = blockIdx.x % 3;
    float dot = 0.f;
    for (int k = threadIdx.x; k < DM; k += 256)
        dot += g_pool[b * DM + k] * fcw[c * DM + k];
    dot = block_sum256(dot);
    float ms = 0.f;
    for (int t = threadIdx.x; t < LL; t += 256)
        ms += (float)mask[b * LL + t];
    ms = block_sum256(ms);
    if (threadIdx.x == 0) out[b * 3 + c] = dot / ms + fcb[c];
}

// ---------------- launch ----------------
extern "C" void kernel_launch(void* const* d_in, const int* in_sizes, int n_in,
                              void* d_out, int out_size) {
    const float* emb      = (const float*)d_in[0];
    const float* norm_w   = (const float*)d_in[1];
    const float* in_proj  = (const float*)d_in[2];
    const float* conv_w   = (const float*)d_in[3];
    const float* conv_b   = (const float*)d_in[4];
    const float* x_proj   = (const float*)d_in[5];
    const float* dt_w     = (const float*)d_in[6];
    const float* dt_b     = (const float*)d_in[7];
    const float* A_log    = (const float*)d_in[8];
    const float* D_skip   = (const float*)d_in[9];
    const float* out_proj = (const float*)d_in[10];
    const float* norm_f   = (const float*)d_in[11];
    const float* fc_w     = (const float*)d_in[12];
    const float* fc_b     = (const float*)d_in[13];
    const int*   ids      = (const int*)d_in[14];
    const int*   mask     = (const int*)d_in[15];
    float* out = (float*)d_out;

    embed_kernel<<<(BL * DM / 4) / 256, 256>>>(emb, ids);

    for (int i = 0; i < NL; i++) {
        rmsnorm_kernel<<<BL, 256>>>(norm_w + (size_t)i * DM);
        // in_proj via HMMA (3-term bf16 split); source g_h bound in device code
        split_a_kernel<DM, 0><<<(BL * DM / 2) / 256, 256>>>();
        split_w_kernel<DM><<<((2 * DI) * DM / 2) / 256, 256>>>(
            in_proj + (size_t)i * 2 * DI * DM);
        hmma_gemm<0><<<dim3(BL / 128, 2 * DI / 128), 256>>>();

        conv_silu_kernel<<<(BL * DI) / 256, 256>>>(
            conv_w + (size_t)i * DI * DC, conv_b + (size_t)i * DI);
        gemm_xproj<<<dim3(XP / 64, BL / 128, KS), 256>>>(x_proj + (size_t)i * XP * DI);
        reduce_xdbl<<<(BL * XP) / 256, 256>>>();
        gemm_tile<1><<<dim3(DI / 128, BL / 128), 256>>>(
            dt_w + (size_t)i * DI * DR, dt_b + (size_t)i * DI);
        scan_kernel<<<dim3(DI / 64, BB), 256>>>(
            A_log + (size_t)i * DI * DS, D_skip + (size_t)i * DI);

        // out_proj via HMMA (residual add); source g_y bound in device code
        split_a_kernel<DI, 1><<<(BL * DI / 2) / 256, 256>>>();
        split_w_kernel<DI><<<(DM * DI / 2) / 256, 256>>>(
            out_proj + (size_t)i * DM * DI);
        hmma_gemm<2><<<dim3(BL / 128, DM / 128), 256>>>();
    }

    rmsnorm_kernel<<<BL, 256>>>(norm_f);
    pool_kernel<<<dim3(DM / 256, BB), 256>>>(mask);
    fc_kernel<<<BB * 3, 256>>>(mask, fc_w, fc_b, out);
}

// round 16
// speedup vs baseline: 2.1104x; 1.0211x over previous
#include <cuda_runtime.h>
#include <cuda_bf16.h>
#include <math.h>
#include <stdint.h>

// ---------------- model constants ----------------
#define NL 2
#define DM 2560
#define DI 5120
#define DS 16
#define DC 4
#define DR 160
#define XP 192          // DR + 2*DS
#define BB 2
#define LL 512
#define BL 1024         // BB*LL
#define KS 8            // split-K factor for x_proj

// ---------------- scratch (device globals; no allocation) ----------------
__device__ float g_x[BL * DM];            // residual stream
__device__ float g_h[BL * DM];            // normed activations
__device__ float g_xz[(size_t)BL * 2 * DI];
__device__ float g_xc[BL * DI];           // conv+silu output (= u)
__device__ float g_delta[BL * DI];
__device__ float g_y[BL * DI];            // gated scan output
__device__ float g_xdbl[BL * XP];
__device__ float g_part[(size_t)KS * BL * XP];
__device__ float g_pool[BB * DM];
// bf16 2-segment split operands: A2 = [Ah|Al] (M x 2K), W2 = [Wh|Wl] (N x 2K).
// The GEMM iterates a VIRTUAL K'=3K via per-chunk base offsets:
//   seg0: Ah*Wh, seg1: Al*Wh, seg2: Ah*Wl  (same order as the old [Ah|Al|Ah]x[Wh|Wh|Wl])
__device__ __nv_bfloat16 g_asplit[(size_t)BL * 2 * DI];
__device__ __nv_bfloat16 g_wsplit[(size_t)(2 * DI) * 2 * DM];

// ---------------- f32x2 packed helpers ----------------
typedef unsigned long long ull;
__device__ __forceinline__ ull dup2(float a) {
    ull r; asm("mov.b64 %0, {%1, %1};" : "=l"(r) : "f"(a)); return r;
}
__device__ __forceinline__ ull fma2_(ull a, ull b, ull c) {
    ull d; asm("fma.rn.f32x2 %0, %1, %2, %3;" : "=l"(d) : "l"(a), "l"(b), "l"(c)); return d;
}
__device__ __forceinline__ float2 unpack2(ull v) {
    float2 r; asm("mov.b64 {%0, %1}, %2;" : "=f"(r.x), "=f"(r.y) : "l"(v)); return r;
}

__device__ __forceinline__ float ex2f(float x) {
    float r; asm("ex2.approx.f32 %0, %1;" : "=f"(r) : "f"(x)); return r;
}
__device__ __forceinline__ float sigmoidf_(float x) {
    return 1.f / (1.f + __expf(-x));
}

// ---------------- HMMA primitive (baseline PTX ISA) ----------------
__device__ __forceinline__ void mma16816(float* c, const uint32_t* a, const uint32_t* b) {
    asm volatile(
        "mma.sync.aligned.m16n8k16.row.col.f32.bf16.bf16.f32 "
        "{%0,%1,%2,%3}, {%4,%5,%6,%7}, {%8,%9}, {%0,%1,%2,%3};"
        : "+f"(c[0]), "+f"(c[1]), "+f"(c[2]), "+f"(c[3])
        : "r"(a[0]), "r"(a[1]), "r"(a[2]), "r"(a[3]), "r"(b[0]), "r"(b[1]));
}

__device__ __forceinline__ float block_sum256(float v) {
    __shared__ float sh[8];
    #pragma unroll
    for (int o = 16; o > 0; o >>= 1) v += __shfl_xor_sync(0xffffffffu, v, o);
    __syncthreads();
    if ((threadIdx.x & 31) == 0) sh[threadIdx.x >> 5] = v;
    __syncthreads();
    v = sh[threadIdx.x & 7];
    #pragma unroll
    for (int o = 4; o > 0; o >>= 1) v += __shfl_xor_sync(0xffffffffu, v, o);
    return v;
}

// ---------------- embedding gather ----------------
__global__ void __launch_bounds__(256) embed_kernel(const float* __restrict__ emb,
                                                    const int* __restrict__ ids) {
    int idx = blockIdx.x * 256 + threadIdx.x;
    int row = idx / (DM / 4);
    int c   = idx % (DM / 4);
    int id  = ids[row];
    ((float4*)g_x)[idx] = ((const float4*)(emb + (size_t)id * DM))[c];
}

// ---------------- rmsnorm: g_x -> g_h ----------------
__global__ void __launch_bounds__(256) rmsnorm_kernel(const float* __restrict__ w) {
    int row = blockIdx.x;
    const float* xr = g_x + (size_t)row * DM;
    float s = 0.f;
    #pragma unroll
    for (int q = 0; q < DM / 256; q++) {
        float v = xr[threadIdx.x + q * 256];
        s += v * v;
    }
    float tot = block_sum256(s);
    float inv = rsqrtf(tot * (1.f / DM) + 1e-5f);
    float* o = g_h + (size_t)row * DM;
    #pragma unroll
    for (int q = 0; q < DM / 256; q++) {
        int k = threadIdx.x + q * 256;
        o[k] = xr[k] * inv * w[k];
    }
}

// ---------------- bf16 2-segment split conversions ----------------
// Sources bound INSIDE device code (R13 fix: host-side __device__ symbol args
// resolve to the host shadow via GB300 ATS and read zeros).
template <int K, int SRC>   // SRC 0: g_h, 1: g_y
__global__ void __launch_bounds__(256) split_a_kernel() {
    const float* __restrict__ src = (SRC == 0) ? g_h : g_y;
    int idx = blockIdx.x * 256 + threadIdx.x;          // over BL*K/2
    int k2 = idx % (K / 2), m = idx / (K / 2);
    float2 v = *(const float2*)&src[(size_t)m * K + 2 * k2];
    __nv_bfloat16 h0 = __float2bfloat16(v.x), h1 = __float2bfloat16(v.y);
    __nv_bfloat162 hi; hi.x = h0; hi.y = h1;
    __nv_bfloat162 lo;
    lo.x = __float2bfloat16(v.x - __bfloat162float(h0));
    lo.y = __float2bfloat16(v.y - __bfloat162float(h1));
    __nv_bfloat162* dst = (__nv_bfloat162*)(g_asplit + (size_t)m * 2 * K);
    dst[k2] = hi; dst[K / 2 + k2] = lo;
}

template <int K>
__global__ void __launch_bounds__(256) split_w_kernel(const float* __restrict__ W) {
    int idx = blockIdx.x * 256 + threadIdx.x;          // over N*K/2
    int k2 = idx % (K / 2), n = idx / (K / 2);
    float2 v = *(const float2*)&W[(size_t)n * K + 2 * k2];
    __nv_bfloat16 h0 = __float2bfloat16(v.x), h1 = __float2bfloat16(v.y);
    __nv_bfloat162 hi; hi.x = h0; hi.y = h1;
    __nv_bfloat162 lo;
    lo.x = __float2bfloat16(v.x - __bfloat162float(h0));
    lo.y = __float2bfloat16(v.y - __bfloat162float(h1));
    __nv_bfloat162* dst = (__nv_bfloat162*)(g_wsplit + (size_t)n * 2 * K);
    dst[k2] = hi; dst[K / 2 + k2] = lo;
}

// ---------------- HMMA bf16 GEMM: C[M,N] = sum over 3 virtual segments ----------------
// 128x128 CTA, 8 warps = 2(M) x 4(N), warp tile 64x32, K-chunk 64 bf16.
// Dynamic smem, DOUBLE-buffered (2 x 36864 = 73728B) -> one bar per chunk,
// STS overlapped with compute. Fragment loads: padded pitch 144B, LDS.32,
// word-bank = 4*gid + tig (conflict-free) — byte-identical to the R15 kernel.
// MODE 0: -> g_xz (NT=10240, K=2560, plain store)
// MODE 2: -> g_x  (NT=2560,  K=5120, residual +=)
#define PA 144
#define TILEB (128 * PA)           // 18432 per operand tile
#define BUFB  (2 * TILEB)          // 36864 per stage (A+B)
#define HG_SMEM (2 * BUFB)         // 73728 double-buffered

template <int MODE>
__global__ void __launch_bounds__(256) hmma_gemm() {
    constexpr int NT  = (MODE == 0) ? 2 * DI : DM;
    constexpr int K   = (MODE == 0) ? DM : DI;        // original reduction dim
    constexpr int KP2 = 2 * K;                        // stored row stride
    constexpr int CPS = K / 64;                       // chunks per segment
    constexpr int T   = 3 * CPS;                      // virtual K' = 3K
    float* __restrict__ C = (MODE == 0) ? g_xz : g_x;

    extern __shared__ __align__(16) char smem[];
    const int bm = blockIdx.x * 128, bn = blockIdx.y * 128;
    const int tid = threadIdx.x, lane = tid & 31, wid = tid >> 5;
    const int wm = wid & 1, wn = wid >> 1;
    const int gid = lane >> 2, tig = lane & 3;

    const __nv_bfloat16* __restrict__ gA = g_asplit;
    const __nv_bfloat16* __restrict__ gB = g_wsplit;

    float acc[4][4][4];
    #pragma unroll
    for (int i = 0; i < 4; i++)
        #pragma unroll
        for (int j = 0; j < 4; j++)
            #pragma unroll
            for (int v = 0; v < 4; v++) acc[i][j][v] = 0.f;

    uint4 ra[4], rb[4];

    auto gload = [&](int t) {
        const int seg = t / CPS;                    // 0: Ah*Wh, 1: Al*Wh, 2: Ah*Wl
        const int kin = (t - seg * CPS) * 64;
        const int aoff = ((seg == 1) ? K : 0) + kin;
        const int woff = ((seg == 2) ? K : 0) + kin;
        #pragma unroll
        for (int q = 0; q < 4; q++) {
            int e = tid + q * 256;                  // 0..1023 = 128 rows x 8 x 16B
            int row = e >> 3, cb = e & 7;
            ra[q] = *(const uint4*)(gA + (size_t)(bm + row) * KP2 + aoff + cb * 8);
            rb[q] = *(const uint4*)(gB + (size_t)(bn + row) * KP2 + woff + cb * 8);
        }
    };
    auto sts = [&](int buf) {
        char* Ab = smem + buf * BUFB;
        char* Bb = Ab + TILEB;
        #pragma unroll
        for (int q = 0; q < 4; q++) {
            int e = tid + q * 256;
            int row = e >> 3, cb = e & 7;
            int off = row * PA + cb * 16;
            *(uint4*)(Ab + off) = ra[q];
            *(uint4*)(Bb + off) = rb[q];
        }
    };

    gload(0); sts(0);
    __syncthreads();

    for (int t = 0; t < T; t++) {
        if (t + 1 < T) gload(t + 1);

        const char* Ab = smem + (t & 1) * BUFB;
        const char* Bb = Ab + TILEB;
        #pragma unroll
        for (int kk = 0; kk < 4; kk++) {
            // a-frag: A[gid][2tig..], A[gid+8][..], A[gid][2tig+8..], A[gid+8][2tig+8..]
            uint32_t a[4][4];
            #pragma unroll
            for (int i = 0; i < 4; i++) {
                const char* p = Ab + (wm * 64 + i * 16 + gid) * PA + kk * 32 + tig * 4;
                a[i][0] = *(const uint32_t*)(p);
                a[i][1] = *(const uint32_t*)(p + 8 * PA);
                a[i][2] = *(const uint32_t*)(p + 16);
                a[i][3] = *(const uint32_t*)(p + 8 * PA + 16);
            }
            // b-frag (NT): b0 = W[n=gid][k=2tig..+1], b1 = +8 in k
            uint32_t b[4][2];
            #pragma unroll
            for (int j = 0; j < 4; j++) {
                const char* p = Bb + (wn * 32 + j * 8 + gid) * PA + kk * 32 + tig * 4;
                b[j][0] = *(const uint32_t*)(p);
                b[j][1] = *(const uint32_t*)(p + 16);
            }
            #pragma unroll
            for (int i = 0; i < 4; i++)
                #pragma unroll
                for (int j = 0; j < 4; j++)
                    mma16816(acc[i][j], a[i], b[j]);
        }

        if (t + 1 < T) {
            sts((t + 1) & 1);   // writes the OTHER buffer; no bar needed vs compute
            __syncthreads();    // one bar per chunk: publish next buf, free cur buf
        }
    }

    // epilogue: c-frag rows gid/gid+8, cols 2tig..+1
    #pragma unroll
    for (int i = 0; i < 4; i++) {
        #pragma unroll
        for (int j = 0; j < 4; j++) {
            int r0 = bm + wm * 64 + i * 16 + gid;
            int c0 = bn + wn * 32 + j * 8 + tig * 2;
            float* p0 = &C[(size_t)r0 * NT + c0];
            float* p1 = &C[(size_t)(r0 + 8) * NT + c0];
            float v0 = acc[i][j][0], v1 = acc[i][j][1];
            float v2 = acc[i][j][2], v3 = acc[i][j][3];
            if (MODE == 2) {
                float2 o0 = *(const float2*)p0;
                float2 o1 = *(const float2*)p1;
                v0 += o0.x; v1 += o0.y; v2 += o1.x; v3 += o1.y;
            }
            *(float2*)p0 = make_float2(v0, v1);
            *(float2*)p1 = make_float2(v2, v3);
        }
    }
}

// ---------------- FFMA2 SGEMM for dt_proj (softplus epilogue) ----------------
template <int MODE>
__global__ void __launch_bounds__(256, 2) gemm_tile(const float* __restrict__ W,
                                                    const float* __restrict__ bias) {
    constexpr int K   = DR;
    constexpr int LDA = XP;
    constexpr int LDC = DI;
    const float* __restrict__ A = g_xdbl;
    float* __restrict__ C       = g_delta;

    __shared__ float As[16][132];
    __shared__ float Bs[16][132];
    const int bm  = blockIdx.y * 128;
    const int bn  = blockIdx.x * 128;
    const int tid = threadIdx.x;
    const int tx  = tid & 15;
    const int ty  = tid >> 4;
    const int lr  = tid >> 2;
    const int lc  = (tid & 3) * 4;

    ull acc[8][4];
    #pragma unroll
    for (int i = 0; i < 8; i++)
        #pragma unroll
        for (int j = 0; j < 4; j++) acc[i][j] = 0ull;

    float4 va[2], vb[2];
    #pragma unroll
    for (int rr = 0; rr < 2; rr++) {
        va[rr] = *(const float4*)&A[(size_t)(bm + lr + rr * 64) * LDA + lc];
        vb[rr] = *(const float4*)&W[(size_t)(bn + lr + rr * 64) * K + lc];
    }

    for (int k0 = 0; k0 < K; k0 += 16) {
        #pragma unroll
        for (int rr = 0; rr < 2; rr++) {
            As[lc + 0][lr + rr * 64] = va[rr].x; As[lc + 1][lr + rr * 64] = va[rr].y;
            As[lc + 2][lr + rr * 64] = va[rr].z; As[lc + 3][lr + rr * 64] = va[rr].w;
            Bs[lc + 0][lr + rr * 64] = vb[rr].x; Bs[lc + 1][lr + rr * 64] = vb[rr].y;
            Bs[lc + 2][lr + rr * 64] = vb[rr].z; Bs[lc + 3][lr + rr * 64] = vb[rr].w;
        }
        __syncthreads();

        const int kn = (k0 + 16 < K) ? (k0 + 16) : 0;
        #pragma unroll
        for (int rr = 0; rr < 2; rr++) {
            va[rr] = *(const float4*)&A[(size_t)(bm + lr + rr * 64) * LDA + kn + lc];
            vb[rr] = *(const float4*)&W[(size_t)(bn + lr + rr * 64) * K + kn + lc];
        }

        #pragma unroll
        for (int k = 0; k < 16; k++) {
            float4 a0 = *(const float4*)&As[k][ty * 8];
            float4 a1 = *(const float4*)&As[k][ty * 8 + 4];
            const ull* bp = (const ull*)&Bs[k][tx * 8];
            ull b2[4] = {bp[0], bp[1], bp[2], bp[3]};
            float ar[8] = {a0.x, a0.y, a0.z, a0.w, a1.x, a1.y, a1.z, a1.w};
            #pragma unroll
            for (int i = 0; i < 8; i++) {
                ull af = dup2(ar[i]);
                #pragma unroll
                for (int jp = 0; jp < 4; jp++)
                    acc[i][jp] = fma2_(af, b2[jp], acc[i][jp]);
            }
        }
        __syncthreads();
    }

    #pragma unroll
    for (int i = 0; i < 8; i++) {
        size_t row = bm + ty * 8 + i;
        #pragma unroll
        for (int jj = 0; jj < 2; jj++) {
            int col = bn + tx * 8 + jj * 4;
            float2 p0 = unpack2(acc[i][jj * 2 + 0]);
            float2 p1 = unpack2(acc[i][jj * 2 + 1]);
            float v0 = p0.x, v1 = p0.y, v2 = p1.x, v3 = p1.y;
            v0 += bias[col + 0]; v1 += bias[col + 1];
            v2 += bias[col + 2]; v3 += bias[col + 3];
            v0 = (v0 > 20.f) ? v0 : log1pf(__expf(v0));
            v1 = (v1 > 20.f) ? v1 : log1pf(__expf(v1));
            v2 = (v2 > 20.f) ? v2 : log1pf(__expf(v2));
            v3 = (v3 > 20.f) ? v3 : log1pf(__expf(v3));
            *(float4*)&C[row * LDC + col] = make_float4(v0, v1, v2, v3);
        }
    }
}

// ---------------- depthwise causal conv1d + SiLU ----------------
__global__ void __launch_bounds__(256) conv_silu_kernel(const float* __restrict__ cw,
                                                        const float* __restrict__ cb) {
    int idx = blockIdx.x * 256 + threadIdx.x;
    int d = idx % DI;
    int r = idx / DI;
    int t = r & (LL - 1);
    float4 wv4 = ((const float4*)cw)[d];
    float wv[4] = {wv4.x, wv4.y, wv4.z, wv4.w};
    float acc = cb[d];
    if (t >= 3) {
        acc += wv[0] * g_xz[(size_t)(r - 3) * 2 * DI + d]
             + wv[1] * g_xz[(size_t)(r - 2) * 2 * DI + d]
             + wv[2] * g_xz[(size_t)(r - 1) * 2 * DI + d]
             + wv[3] * g_xz[(size_t)(r    ) * 2 * DI + d];
    } else {
        #pragma unroll
        for (int k = 0; k < 4; k++) {
            int tt = t - 3 + k;
            if (tt >= 0) acc += wv[k] * g_xz[(size_t)(r - 3 + k) * 2 * DI + d];
        }
    }
    g_xc[idx] = acc * sigmoidf_(acc);
}

// ---------------- x_proj split-K (FFMA2) ----------------
__global__ void __launch_bounds__(256, 2) gemm_xproj(const float* __restrict__ W) {
    __shared__ float As[16][132];
    __shared__ float Bs[16][68];
    const int bn  = blockIdx.x * 64;
    const int bm  = blockIdx.y * 128;
    const int ks  = blockIdx.z;
    const int tid = threadIdx.x;
    const int tx  = tid & 15;
    const int ty  = tid >> 4;
    const int lr  = tid >> 2;
    const int lc  = (tid & 3) * 4;

    ull acc[8][2];
    #pragma unroll
    for (int i = 0; i < 8; i++) { acc[i][0] = 0ull; acc[i][1] = 0ull; }

    const int kb = ks * (DI / KS);

    float4 va[2], vb;
    #pragma unroll
    for (int rr = 0; rr < 2; rr++)
        va[rr] = *(const float4*)&g_xc[(size_t)(bm + lr + rr * 64) * DI + kb + lc];
    vb = *(const float4*)&W[(size_t)(bn + lr) * DI + kb + lc];

    for (int k0 = kb; k0 < kb + DI / KS; k0 += 16) {
        #pragma unroll
        for (int rr = 0; rr < 2; rr++) {
            As[lc + 0][lr + rr * 64] = va[rr].x; As[lc + 1][lr + rr * 64] = va[rr].y;
            As[lc + 2][lr + rr * 64] = va[rr].z; As[lc + 3][lr + rr * 64] = va[rr].w;
        }
        Bs[lc + 0][lr] = vb.x; Bs[lc + 1][lr] = vb.y;
        Bs[lc + 2][lr] = vb.z; Bs[lc + 3][lr] = vb.w;
        __syncthreads();

        const int kn = (k0 + 16 < kb + DI / KS) ? (k0 + 16) : kb;
        #pragma unroll
        for (int rr = 0; rr < 2; rr++)
            va[rr] = *(const float4*)&g_xc[(size_t)(bm + lr + rr * 64) * DI + kn + lc];
        vb = *(const float4*)&W[(size_t)(bn + lr) * DI + kn + lc];

        #pragma unroll
        for (int k = 0; k < 16; k++) {
            float4 a0 = *(const float4*)&As[k][ty * 8];
            float4 a1 = *(const float4*)&As[k][ty * 8 + 4];
            const ull* bp = (const ull*)&Bs[k][tx * 4];
            ull b2[2] = {bp[0], bp[1]};
            float ar[8] = {a0.x, a0.y, a0.z, a0.w, a1.x, a1.y, a1.z, a1.w};
            #pragma unroll
            for (int i = 0; i < 8; i++) {
                ull af = dup2(ar[i]);
                acc[i][0] = fma2_(af, b2[0], acc[i][0]);
                acc[i][1] = fma2_(af, b2[1], acc[i][1]);
            }
        }
        __syncthreads();
    }
    #pragma unroll
    for (int i = 0; i < 8; i++) {
        float2 p0 = unpack2(acc[i][0]);
        float2 p1 = unpack2(acc[i][1]);
        *(float4*)&g_part[((size_t)ks * BL + bm + ty * 8 + i) * XP + bn + tx * 4] =
            make_float4(p0.x, p0.y, p1.x, p1.y);
    }
}

__global__ void __launch_bounds__(256) reduce_xdbl() {
    int idx = blockIdx.x * 256 + threadIdx.x;
    float s = 0.f;
    #pragma unroll
    for (int k = 0; k < KS; k++) s += g_part[(size_t)k * BL * XP + idx];
    g_xdbl[idx] = s;
}

// ---------------- selective scan (fused gate) ----------------
__global__ void __launch_bounds__(256) scan_kernel(const float* __restrict__ A_log,
                                                   const float* __restrict__ Dskip) {
    const int b  = blockIdx.y;
    const int d0 = blockIdx.x * 64;
    const int tid = threadIdx.x;
    const int dl = tid >> 2;
    const int ng = tid & 3;
    const int d  = d0 + dl;

    __shared__ float sd[32][64], su[32][64], sB[32][16], sC[32][16], sy[32][64];

    const float LOG2E = 1.4426950408889634f;
    float A2[4], h[4];
    #pragma unroll
    for (int j = 0; j < 4; j++) {
        A2[j] = -__expf(A_log[d * DS + ng * 4 + j]) * LOG2E;
        h[j] = 0.f;
    }
    const float Dv = Dskip[d];

    for (int t0 = 0; t0 < LL; t0 += 32) {
        #pragma unroll
        for (int q = 0; q < 8; q++) {
            int e = tid + q * 256;
            int i = e >> 6, c = e & 63;
            size_t g = (size_t)(b * LL + t0 + i) * DI + d0 + c;
            sd[i][c] = g_delta[g];
            su[i][c] = g_xc[g];
        }
        #pragma unroll
        for (int q = 0; q < 2; q++) {
            int e = tid + q * 256;
            int i = e >> 4, n = e & 15;
            size_t g = (size_t)(b * LL + t0 + i) * XP;
            sB[i][n] = g_xdbl[g + DR + n];
            sC[i][n] = g_xdbl[g + DR + DS + n];
        }
        __syncthreads();

        #pragma unroll 4
        for (int i = 0; i < 32; i++) {
            float dlt = sd[i][dl];
            float uu  = su[i][dl];
            float du  = dlt * uu;
            float p = 0.f;
            #pragma unroll
            for (int j = 0; j < 4; j++) {
                float dA = ex2f(dlt * A2[j]);
                h[j] = dA * h[j] + du * sB[i][ng * 4 + j];
                p += h[j] * sC[i][ng * 4 + j];
            }
            p += __shfl_xor_sync(0xffffffffu, p, 1);
            p += __shfl_xor_sync(0xffffffffu, p, 2);
            if (ng == 0) sy[i][dl] = p + uu * Dv;
        }
        __syncthreads();

        #pragma unroll
        for (int q = 0; q < 8; q++) {
            int e = tid + q * 256;
            int i = e >> 6, c = e & 63;
            size_t r = (size_t)(b * LL + t0 + i);
            float z = g_xz[r * 2 * DI + DI + d0 + c];
            g_y[r * DI + d0 + c] = sy[i][c] * (z * sigmoidf_(z));
        }
        __syncthreads();
    }
}

// ---------------- masked pooling + classifier ----------------
__global__ void __launch_bounds__(256) pool_kernel(const int* __restrict__ mask) {
    int b  = blockIdx.y;
    int dm = blockIdx.x * 256 + threadIdx.x;
    float s = 0.f;
    #pragma unroll 8
    for (int t = 0; t < LL; t++) {
        s += g_h[(size_t)(b * LL + t) * DM + dm] * (float)mask[b * LL + t];
    }
    g_pool[b * DM + dm] = s;
}

__global__ void __launch_bounds__(256) fc_kernel(const int* __restrict__ mask,
                                                 const float* __restrict__ fcw,
                                                 const float* __restrict__ fcb,
                                                 float* __restrict__ out) {
    int b = blockIdx.x / 3, c = blockIdx.x % 3;
    float dot = 0.f;
    for (int k = threadIdx.x; k < DM; k += 256)
        dot += g_pool[b * DM + k] * fcw[c * DM + k];
    dot = block_sum256(dot);
    float ms = 0.f;
    for (int t = threadIdx.x; t < LL; t += 256)
        ms += (float)mask[b * LL + t];
    ms = block_sum256(ms);
    if (threadIdx.x == 0) out[b * 3 + c] = dot / ms + fcb[c];
}

// ---------------- launch ----------------
extern "C" void kernel_launch(void* const* d_in, const int* in_sizes, int n_in,
                              void* d_out, int out_size) {
    const float* emb      = (const float*)d_in[0];
    const float* norm_w   = (const float*)d_in[1];
    const float* in_proj  = (const float*)d_in[2];
    const float* conv_w   = (const float*)d_in[3];
    const float* conv_b   = (const float*)d_in[4];
    const float* x_proj   = (const float*)d_in[5];
    const float* dt_w     = (const float*)d_in[6];
    const float* dt_b     = (const float*)d_in[7];
    const float* A_log    = (const float*)d_in[8];
    const float* D_skip   = (const float*)d_in[9];
    const float* out_proj = (const float*)d_in[10];
    const float* norm_f   = (const float*)d_in[11];
    const float* fc_w     = (const float*)d_in[12];
    const float* fc_b     = (const float*)d_in[13];
    const int*   ids      = (const int*)d_in[14];
    const int*   mask     = (const int*)d_in[15];
    float* out = (float*)d_out;

    cudaFuncSetAttribute(hmma_gemm<0>, cudaFuncAttributeMaxDynamicSharedMemorySize, HG_SMEM);
    cudaFuncSetAttribute(hmma_gemm<2>, cudaFuncAttributeMaxDynamicSharedMemorySize, HG_SMEM);

    embed_kernel<<<(BL * DM / 4) / 256, 256>>>(emb, ids);

    for (int i = 0; i < NL; i++) {
        rmsnorm_kernel<<<BL, 256>>>(norm_w + (size_t)i * DM);
        // in_proj via HMMA (2-segment split, virtual K'=3K)
        split_a_kernel<DM, 0><<<(BL * DM / 2) / 256, 256>>>();
        split_w_kernel<DM><<<((2 * DI) * DM / 2) / 256, 256>>>(
            in_proj + (size_t)i * 2 * DI * DM);
        hmma_gemm<0><<<dim3(BL / 128, 2 * DI / 128), 256, HG_SMEM>>>();

        conv_silu_kernel<<<(BL * DI) / 256, 256>>>(
            conv_w + (size_t)i * DI * DC, conv_b + (size_t)i * DI);
        gemm_xproj<<<dim3(XP / 64, BL / 128, KS), 256>>>(x_proj + (size_t)i * XP * DI);
        reduce_xdbl<<<(BL * XP) / 256, 256>>>();
        gemm_tile<1><<<dim3(DI / 128, BL / 128), 256>>>(
            dt_w + (size_t)i * DI * DR, dt_b + (size_t)i * DI);
        scan_kernel<<<dim3(DI / 64, BB), 256>>>(
            A_log + (size_t)i * DI * DS, D_skip + (size_t)i * DI);

        // out_proj via HMMA (residual add)
        split_a_kernel<DI, 1><<<(BL * DI / 2) / 256, 256>>>();
        split_w_kernel<DI><<<(DM * DI / 2) / 256, 256>>>(
            out_proj + (size_t)i * DM * DI);
        hmma_gemm<2><<<dim3(BL / 128, DM / 128), 256, HG_SMEM>>>();
    }

    rmsnorm_kernel<<<BL, 256>>>(norm_f);
    pool_kernel<<<dim3(DM / 256, BB), 256>>>(mask);
    fc_kernel<<<BB * 3, 256>>>(mask, fc_w, fc_b, out);
}